// round 15
// baseline (speedup 1.0000x reference)
#include <cuda_runtime.h>
#include <cuda_fp16.h>
#include <cstdint>

// ---------------------------------------------------------------------------
// WindowAttention (Swin): x[4096,49,512] -> out[4096,49,512]
//   qkv  = x @ qkv_w + qkv_b            (M=200704, K=512, N=1536)
//   attn = softmax(q k^T * scale + rel_bias) v     (per window, head)
//   out  = attn @ proj_w + proj_b       (M=200704, K=512, N=512)
// Legacy mma.sync (HMMA) path. fp16 operands, fp32 accumulation.
// GEMM: CTA 128x128, 4 warps (64x64 warp tile), kblock 64, 3-stage cp.async,
// single-sync pipeline + interleaved fill quarters + B-fragment double
// buffering (B frags for step s+1 load under step s's MMAs).
// conv_wT: smem-tiled transpose (both sides coalesced).
// ---------------------------------------------------------------------------

#define DIMC    512
#define NHEADS  16
#define HDIM    32
#define NTOK    49
#define NWIN    4096
#define MTOT    (NWIN * NTOK)          // 200704 = 1568 * 128 exactly

// Static device scratch (no runtime allocation allowed).
__device__ __align__(128) __half g_x_h[(size_t)MTOT * 512];
__device__ __align__(128) __half g_qkv_h[(size_t)MTOT * 1536];
__device__ __align__(128) __half g_attn_h[(size_t)MTOT * 512];
__device__ __align__(128) __half g_wq[(size_t)1536 * 512];     // qkv_w^T  [n][k]
__device__ __align__(128) __half g_wp[(size_t)512 * 512];      // proj_w^T [n][k]
__device__ __align__(128) __half g_biasp[NHEADS * 64 * 64];    // padded+masked fp16 bias

// ---------------------------------------------------------------------------
// helpers
// ---------------------------------------------------------------------------
__device__ __forceinline__ uint32_t smem_u32(const void* p) {
    uint32_t a;
    asm("{ .reg .u64 t; cvta.to.shared.u64 t, %1; cvt.u32.u64 %0, t; }" : "=r"(a) : "l"(p));
    return a;
}
__device__ __forceinline__ void mma16816(float c[4], const unsigned a[4], const unsigned b[2]) {
    asm volatile(
        "mma.sync.aligned.m16n8k16.row.col.f32.f16.f16.f32 "
        "{%0,%1,%2,%3}, {%4,%5,%6,%7}, {%8,%9}, {%0,%1,%2,%3};\n"
        : "+f"(c[0]), "+f"(c[1]), "+f"(c[2]), "+f"(c[3])
        : "r"(a[0]), "r"(a[1]), "r"(a[2]), "r"(a[3]), "r"(b[0]), "r"(b[1]));
}
__device__ __forceinline__ unsigned f2h2(float lo, float hi) {
    __half2 h = __floats2half2_rn(lo, hi);
    return *reinterpret_cast<unsigned*>(&h);
}
#define LDSM_X4(r0, r1, r2, r3, addr) \
    asm volatile("ldmatrix.sync.aligned.m8n8.x4.shared.b16 {%0,%1,%2,%3}, [%4];" \
                 : "=r"(r0), "=r"(r1), "=r"(r2), "=r"(r3) : "r"(addr))
#define LDSM_X4T(r0, r1, r2, r3, addr) \
    asm volatile("ldmatrix.sync.aligned.m8n8.x4.trans.shared.b16 {%0,%1,%2,%3}, [%4];" \
                 : "=r"(r0), "=r"(r1), "=r"(r2), "=r"(r3) : "r"(addr))
#define CP_ASYNC16(dst, src) \
    asm volatile("cp.async.cg.shared.global [%0], [%1], 16;\n" :: "r"(dst), "l"(src))
#define CP_COMMIT() asm volatile("cp.async.commit_group;\n" ::: "memory")
#define CP_WAIT1()  asm volatile("cp.async.wait_group 1;\n" ::: "memory")
#define CP_WAIT0()  asm volatile("cp.async.wait_group 0;\n" ::: "memory")

// ---------------------------------------------------------------------------
// prepass kernels
// ---------------------------------------------------------------------------
__global__ void conv_x(const float* __restrict__ in, __half* __restrict__ out, int n4) {
    int i = blockIdx.x * blockDim.x + threadIdx.x;
    if (i < n4) {
        float4 v = reinterpret_cast<const float4*>(in)[i];
        uint2 o;
        o.x = f2h2(v.x, v.y);
        o.y = f2h2(v.z, v.w);
        reinterpret_cast<uint2*>(out)[i] = o;
    }
}
// w[K][Nw] fp32 -> wt[n][k] fp16, smem-tiled (coalesced both sides)
__global__ void conv_wT(const float* __restrict__ w, __half* __restrict__ wt, int K, int Nw) {
    __shared__ float tile[32][33];
    const int n0 = blockIdx.x * 32, k0 = blockIdx.y * 32;
    const int tx = threadIdx.x, ty = threadIdx.y;
#pragma unroll
    for (int i = ty; i < 32; i += 8)
        tile[i][tx] = w[(size_t)(k0 + i) * Nw + n0 + tx];
    __syncthreads();
#pragma unroll
    for (int i = ty; i < 32; i += 8)
        wt[(size_t)(n0 + i) * K + k0 + tx] = __float2half_rn(tile[tx][i]);
}
// gather + pad 49x49 -> 64x64 + mask (-60000 in fp16 => exp underflows to 0)
__global__ void bias_gather(const float* __restrict__ table, const int* __restrict__ idx) {
    int h = blockIdx.x;
    for (int e = threadIdx.x; e < 64 * 64; e += blockDim.x) {
        int i = e >> 6, j = e & 63;
        float v = (i < NTOK && j < NTOK) ? table[idx[i * NTOK + j] * NHEADS + h] : -60000.f;
        g_biasp[h * 4096 + e] = __float2half_rn(v);
    }
}

// ---------------------------------------------------------------------------
// GEMM: C[M][Nn] = A[M][512](half) @ BT[Nn][512]^T + bias
// CTA tile 128x128, kblock 64, 4 warps (2x2), warp tile 64x64.
// smem per stage: A 16KB + B 16KB (swizzled 128B rows). 3 stages = 96KB.
// ---------------------------------------------------------------------------
#define STAGE_BYTES 32768
#define GEMM_SMEM   (3 * STAGE_BYTES)

__device__ __forceinline__ void fill_async(uint32_t stage,
                                           const __half* __restrict__ A,
                                           const __half* __restrict__ BT,
                                           int mBase, int nBase, int kb, int tid) {
#pragma unroll
    for (int q = 0; q < 8; q++) {
        int c = tid + q * 128;
        int row = c >> 3, ch = c & 7;
        const __half* src = A + (size_t)(mBase + row) * 512 + kb + ch * 8;
        uint32_t off = row * 128 + ((ch ^ (row & 7)) * 16);
        CP_ASYNC16(stage + off, src);
    }
#pragma unroll
    for (int q = 0; q < 8; q++) {
        int c = tid + q * 128;
        int row = c >> 3, ch = c & 7;
        const __half* src = BT + (size_t)(nBase + row) * 512 + kb + ch * 8;
        uint32_t off = row * 128 + ((ch ^ (row & 7)) * 16);
        CP_ASYNC16(stage + 16384 + off, src);
    }
}

// quarter q4 (0..3): A chunks 2*q4,2*q4+1 and B chunks 2*q4,2*q4+1
__device__ __forceinline__ void fill_quarter(uint32_t stage,
                                             const __half* __restrict__ A,
                                             const __half* __restrict__ BT,
                                             int mBase, int nBase, int kb,
                                             int tid, int q4) {
#pragma unroll
    for (int q = 2 * q4; q < 2 * q4 + 2; q++) {
        int c = tid + q * 128;
        int row = c >> 3, ch = c & 7;
        const __half* src = A + (size_t)(mBase + row) * 512 + kb + ch * 8;
        uint32_t off = row * 128 + ((ch ^ (row & 7)) * 16);
        CP_ASYNC16(stage + off, src);
    }
#pragma unroll
    for (int q = 2 * q4; q < 2 * q4 + 2; q++) {
        int c = tid + q * 128;
        int row = c >> 3, ch = c & 7;
        const __half* src = BT + (size_t)(nBase + row) * 512 + kb + ch * 8;
        uint32_t off = row * 128 + ((ch ^ (row & 7)) * 16);
        CP_ASYNC16(stage + 16384 + off, src);
    }
}

__device__ __forceinline__ void ldA_frags(uint32_t sA, int wm, int rA, int cA, int kc,
                                          unsigned a[4][4]) {
#pragma unroll
    for (int mi = 0; mi < 4; mi++) {
        int row = wm * 64 + mi * 16 + rA;
        int ch = (kc + cA) ^ (row & 7);
        LDSM_X4(a[mi][0], a[mi][1], a[mi][2], a[mi][3], sA + row * 128 + ch * 16);
    }
}
__device__ __forceinline__ void ldB_frags(uint32_t sB, int wn, int rB, int cB, int kc,
                                          unsigned b[8][2]) {
#pragma unroll
    for (int nj = 0; nj < 4; nj++) {
        int row = wn * 64 + nj * 16 + rB;
        int ch = (kc + cB) ^ (row & 7);
        unsigned r0, r1, r2, r3;
        LDSM_X4(r0, r1, r2, r3, sB + row * 128 + ch * 16);
        b[nj * 2][0] = r0; b[nj * 2][1] = r1;
        b[nj * 2 + 1][0] = r2; b[nj * 2 + 1][1] = r3;
    }
}

template <bool OUT_HALF>
__global__ __launch_bounds__(128, 2) void gemm_f16(
    const __half* __restrict__ A, const __half* __restrict__ BT,
    const float* __restrict__ bias, void* __restrict__ Cout, int Nn)
{
    extern __shared__ __align__(1024) char smem[];
    const uint32_t sb = smem_u32(smem);
    const int tid = threadIdx.x;
    const int w = tid >> 5, lane = tid & 31;
    const int wm = w >> 1, wn = w & 1;               // 2x2 warp grid, tile 64x64
    const int g = lane >> 2, t = lane & 3;
    const int mBase = blockIdx.y * 128;
    const int nBase = blockIdx.x * 128;

    float acc[4][8][4];
#pragma unroll
    for (int mi = 0; mi < 4; mi++)
#pragma unroll
        for (int ni = 0; ni < 8; ni++)
#pragma unroll
            for (int c = 0; c < 4; c++) acc[mi][ni][c] = 0.f;

    // prologue: fill stages 0,1
    fill_async(sb + 0 * STAGE_BYTES, A, BT, mBase, nBase, 0, tid);
    CP_COMMIT();
    fill_async(sb + 1 * STAGE_BYTES, A, BT, mBase, nBase, 64, tid);
    CP_COMMIT();

    const int rA = lane & 15;                        // ldmatrix A lane->row
    const int cA = lane >> 4;
    const int rB = (lane & 7) + ((lane >> 1) & 8);   // ldmatrix B lane->row
    const int cB = (lane >> 3) & 1;

    // single-sync pipeline; B frags double-buffered across k16 steps;
    // fill quarters issued inside the per-step latency windows
#pragma unroll
    for (int it = 0; it < 8; ++it) {                 // K = 8 * 64
        if (it < 7) { CP_WAIT1(); } else { CP_WAIT0(); }
        __syncthreads();
        const uint32_t cst = sb + (it % 3) * STAGE_BYTES;
        const uint32_t fst = sb + ((it + 2) % 3) * STAGE_BYTES;
        const int fkb = (it + 2) * 64;
        const bool doFill = (it < 6);
        const uint32_t sA = cst, sB = cst + 16384;

        unsigned b0[8][2], b1[8][2];
        ldB_frags(sB, wn, rB, cB, 0, b0);

#pragma unroll
        for (int step = 0; step < 4; ++step) {       // 4 x k16
            unsigned (*bc)[2] = (step & 1) ? b1 : b0;
            unsigned (*bn)[2] = (step & 1) ? b0 : b1;
            unsigned a[4][4];
            ldA_frags(sA, wm, rA, cA, step * 2, a);
            if (step < 3)
                ldB_frags(sB, wn, rB, cB, (step + 1) * 2, bn);
            if (doFill)
                fill_quarter(fst, A, BT, mBase, nBase, fkb, tid, step);
#pragma unroll
            for (int mi = 0; mi < 4; mi++)
#pragma unroll
                for (int ni = 0; ni < 8; ni++)
                    mma16816(acc[mi][ni], a[mi], bc[ni]);
        }
        if (doFill) CP_COMMIT();
    }

    // epilogue: + bias, store (all dims exact multiples -> no guards)
#pragma unroll
    for (int mi = 0; mi < 4; mi++) {
        int r0 = mBase + wm * 64 + mi * 16 + g;
#pragma unroll
        for (int ni = 0; ni < 8; ni++) {
            int c = nBase + wn * 64 + ni * 8 + 2 * t;
            float b0v = bias[c], b1v = bias[c + 1];
            if (OUT_HALF) {
                __half* o = reinterpret_cast<__half*>(Cout);
                *reinterpret_cast<unsigned*>(o + (size_t)r0 * Nn + c) =
                    f2h2(acc[mi][ni][0] + b0v, acc[mi][ni][1] + b1v);
                *reinterpret_cast<unsigned*>(o + (size_t)(r0 + 8) * Nn + c) =
                    f2h2(acc[mi][ni][2] + b0v, acc[mi][ni][3] + b1v);
            } else {
                float* o = reinterpret_cast<float*>(Cout);
                *reinterpret_cast<float2*>(o + (size_t)r0 * Nn + c) =
                    make_float2(acc[mi][ni][0] + b0v, acc[mi][ni][1] + b1v);
                *reinterpret_cast<float2*>(o + (size_t)(r0 + 8) * Nn + c) =
                    make_float2(acc[mi][ni][2] + b0v, acc[mi][ni][3] + b1v);
            }
        }
    }
}

// ---------------------------------------------------------------------------
// fused attention per (window, head) — R7 configuration. 4 warps,
// M/N padded 49->64. Q,K,V stored [token][d]; V B-fragments via
// ldmatrix.trans. Bias read per-thread from pre-padded fp16 gmem (L2-hot).
// ---------------------------------------------------------------------------
__global__ __launch_bounds__(128) void attn_kernel()
{
    __shared__ __align__(16) __half sQ[64][40];   // [m][d]  (80B rows)
    __shared__ __align__(16) __half sK[64][40];   // [j][d]
    __shared__ __align__(16) __half sV[64][40];   // [j][d]

    const int win = blockIdx.x, head = blockIdx.y;
    const int tid = threadIdx.x;
    const int w = tid >> 5, lane = tid & 31;
    const int g = lane >> 2, t = lane & 3;
    const uint32_t qB = smem_u32(&sQ[0][0]);
    const uint32_t kB = smem_u32(&sK[0][0]);
    const uint32_t vB = smem_u32(&sV[0][0]);

    // zero only pad rows 48..63 (cols 0..31), all 3 arrays
    {
        const uint4 z4 = make_uint4(0u, 0u, 0u, 0u);
        for (int e = tid; e < 192; e += 128) {
            int a = e >> 6, r = 48 + ((e >> 2) & 15), c = e & 3;
            __half* base = (a == 0) ? &sQ[r][c * 8] : (a == 1) ? &sK[r][c * 8] : &sV[r][c * 8];
            *reinterpret_cast<uint4*>(base) = z4;
        }
    }
    __syncthreads();

    // load Q,K,V rows (49 rows x 4 x 16B each)
    const size_t rowbase = (size_t)(win * NTOK) * 1536;
    for (int e = tid; e < 588; e += 128) {
        int which = e / 196, ee = e - which * 196;
        int i = ee >> 2, c = ee & 3;
        uint4 v = *reinterpret_cast<const uint4*>(
            g_qkv_h + rowbase + (size_t)i * 1536 + which * 512 + head * HDIM + c * 8);
        __half* dst = (which == 0) ? &sQ[i][c * 8] : (which == 1) ? &sK[i][c * 8] : &sV[i][c * 8];
        *reinterpret_cast<uint4*>(dst) = v;
    }
    __syncthreads();

    // ---- S = Q K^T (per warp m16 x n64 x k32), ldmatrix fragments ----
    float sacc[8][4];
#pragma unroll
    for (int ni = 0; ni < 8; ni++)
#pragma unroll
        for (int c = 0; c < 4; c++) sacc[ni][c] = 0.f;

    const int rA = lane & 15, cA = lane >> 4;
    const int rB = (lane & 7) + ((lane >> 1) & 8), cB = (lane >> 3) & 1;
#pragma unroll
    for (int ks = 0; ks < 2; ++ks) {
        unsigned a[4];
        {
            int row = w * 16 + rA;
            LDSM_X4(a[0], a[1], a[2], a[3], qB + row * 80 + (ks * 2 + cA) * 16);
        }
        unsigned b[8][2];
#pragma unroll
        for (int nj = 0; nj < 4; nj++) {
            int row = nj * 16 + rB;
            unsigned r0v, r1v, r2v, r3v;
            LDSM_X4(r0v, r1v, r2v, r3v, kB + row * 80 + (ks * 2 + cB) * 16);
            b[nj * 2][0] = r0v; b[nj * 2][1] = r1v;
            b[nj * 2 + 1][0] = r2v; b[nj * 2 + 1][1] = r3v;
        }
#pragma unroll
        for (int ni = 0; ni < 8; ni++)
            mma16816(sacc[ni], a, b[ni]);
    }

    // ---- scale + bias (fp16 gmem, L2-hot) + softmax ----
    const float scale = 0.17677669529663689f;   // 32^-0.5
    const int r0 = w * 16 + g;
    const __half* bp = g_biasp + head * 4096;
    float mA = -1e38f, mB = -1e38f;
#pragma unroll
    for (int ni = 0; ni < 8; ni++) {
        int c0 = ni * 8 + 2 * t;
        float2 bA = __half22float2(*reinterpret_cast<const __half2*>(bp + r0 * 64 + c0));
        float2 bBv = __half22float2(*reinterpret_cast<const __half2*>(bp + (r0 + 8) * 64 + c0));
        sacc[ni][0] = fmaf(sacc[ni][0], scale, bA.x);
        sacc[ni][1] = fmaf(sacc[ni][1], scale, bA.y);
        sacc[ni][2] = fmaf(sacc[ni][2], scale, bBv.x);
        sacc[ni][3] = fmaf(sacc[ni][3], scale, bBv.y);
        mA = fmaxf(mA, fmaxf(sacc[ni][0], sacc[ni][1]));
        mB = fmaxf(mB, fmaxf(sacc[ni][2], sacc[ni][3]));
    }
    mA = fmaxf(mA, __shfl_xor_sync(0xffffffffu, mA, 1));
    mA = fmaxf(mA, __shfl_xor_sync(0xffffffffu, mA, 2));
    mB = fmaxf(mB, __shfl_xor_sync(0xffffffffu, mB, 1));
    mB = fmaxf(mB, __shfl_xor_sync(0xffffffffu, mB, 2));

    float sumA = 0.f, sumB = 0.f;
#pragma unroll
    for (int ni = 0; ni < 8; ni++) {
        sacc[ni][0] = __expf(sacc[ni][0] - mA);
        sacc[ni][1] = __expf(sacc[ni][1] - mA);
        sacc[ni][2] = __expf(sacc[ni][2] - mB);
        sacc[ni][3] = __expf(sacc[ni][3] - mB);
        sumA += sacc[ni][0] + sacc[ni][1];
        sumB += sacc[ni][2] + sacc[ni][3];
    }
    sumA += __shfl_xor_sync(0xffffffffu, sumA, 1);
    sumA += __shfl_xor_sync(0xffffffffu, sumA, 2);
    sumB += __shfl_xor_sync(0xffffffffu, sumB, 1);
    sumB += __shfl_xor_sync(0xffffffffu, sumB, 2);
    const float invA = 1.f / sumA, invB = 1.f / sumB;

    // ---- O = P V (per warp m16 x n32 x k64); V frags via ldmatrix.trans ----
    float oacc[4][4];
#pragma unroll
    for (int ni = 0; ni < 4; ni++)
#pragma unroll
        for (int c = 0; c < 4; c++) oacc[ni][c] = 0.f;

    const int rV = (lane & 7) + (lane & 8);
    const int cV = (lane >> 4) << 3;
#pragma unroll
    for (int ks = 0; ks < 4; ++ks) {
        unsigned a[4];
        a[0] = f2h2(sacc[2 * ks][0] * invA, sacc[2 * ks][1] * invA);
        a[1] = f2h2(sacc[2 * ks][2] * invB, sacc[2 * ks][3] * invB);
        a[2] = f2h2(sacc[2 * ks + 1][0] * invA, sacc[2 * ks + 1][1] * invA);
        a[3] = f2h2(sacc[2 * ks + 1][2] * invB, sacc[2 * ks + 1][3] * invB);
        const int kk = ks * 16;
        unsigned b[4][2];
#pragma unroll
        for (int njp = 0; njp < 2; njp++) {
            unsigned r0v, r1v, r2v, r3v;
            LDSM_X4T(r0v, r1v, r2v, r3v,
                     vB + (kk + rV) * 80 + (njp * 16 + cV) * 2);
            b[njp * 2][0] = r0v; b[njp * 2][1] = r1v;
            b[njp * 2 + 1][0] = r2v; b[njp * 2 + 1][1] = r3v;
        }
#pragma unroll
        for (int ni = 0; ni < 4; ni++)
            mma16816(oacc[ni], a, b[ni]);
    }

    // ---- write attn-out (half) rows < 49 ----
    if (r0 < NTOK) {
        size_t gr = (size_t)(win * NTOK + r0) * 512 + head * HDIM;
#pragma unroll
        for (int ni = 0; ni < 4; ni++)
            *reinterpret_cast<unsigned*>(g_attn_h + gr + ni * 8 + 2 * t) =
                f2h2(oacc[ni][0], oacc[ni][1]);
    }
    if (r0 + 8 < NTOK) {
        size_t gr = (size_t)(win * NTOK + r0 + 8) * 512 + head * HDIM;
#pragma unroll
        for (int ni = 0; ni < 4; ni++)
            *reinterpret_cast<unsigned*>(g_attn_h + gr + ni * 8 + 2 * t) =
                f2h2(oacc[ni][2], oacc[ni][3]);
    }
}

// ---------------------------------------------------------------------------
extern "C" void kernel_launch(void* const* d_in, const int* in_sizes, int n_in,
                              void* d_out, int out_size)
{
    const float* x      = (const float*)d_in[0];
    const float* qkv_w  = (const float*)d_in[1];
    const float* qkv_b  = (const float*)d_in[2];
    const float* proj_w = (const float*)d_in[3];
    const float* proj_b = (const float*)d_in[4];
    const float* table  = (const float*)d_in[5];
    const int*   rpi    = (const int*)d_in[6];
    float* out = (float*)d_out;

    void *xh, *qkvh, *attnh, *wq, *wp;
    cudaGetSymbolAddress(&xh, g_x_h);
    cudaGetSymbolAddress(&qkvh, g_qkv_h);
    cudaGetSymbolAddress(&attnh, g_attn_h);
    cudaGetSymbolAddress(&wq, g_wq);
    cudaGetSymbolAddress(&wp, g_wp);

    cudaFuncSetAttribute(gemm_f16<true>,  cudaFuncAttributeMaxDynamicSharedMemorySize, GEMM_SMEM);
    cudaFuncSetAttribute(gemm_f16<false>, cudaFuncAttributeMaxDynamicSharedMemorySize, GEMM_SMEM);

    const int n4 = MTOT * 512 / 4;
    conv_x<<<n4 / 256, 256>>>(x, (__half*)xh, n4);
    conv_wT<<<dim3(1536 / 32, 512 / 32), dim3(32, 8)>>>(qkv_w, (__half*)wq, 512, 1536);
    conv_wT<<<dim3(512 / 32, 512 / 32), dim3(32, 8)>>>(proj_w, (__half*)wp, 512, 512);
    bias_gather<<<NHEADS, 256>>>(table, rpi);

    gemm_f16<true><<<dim3(1536 / 128, MTOT / 128), 128, GEMM_SMEM>>>(
        (const __half*)xh, (const __half*)wq, qkv_b, qkvh, 1536);
    attn_kernel<<<dim3(NWIN, NHEADS), 128>>>();
    gemm_f16<false><<<dim3(512 / 128, MTOT / 128), 128, GEMM_SMEM>>>(
        (const __half*)attnh, (const __half*)wp, proj_b, out, 512);
}

// round 16
// speedup vs baseline: 1.0018x; 1.0018x over previous
#include <cuda_runtime.h>
#include <cuda_fp16.h>
#include <cstdint>

// ---------------------------------------------------------------------------
// WindowAttention (Swin): x[4096,49,512] -> out[4096,49,512]
//   qkv  = x @ qkv_w + qkv_b            (M=200704, K=512, N=1536)
//   attn = softmax(q k^T * scale + rel_bias) v     (per window, head)
//   out  = attn @ proj_w + proj_b       (M=200704, K=512, N=512)
// Legacy mma.sync (HMMA) path. fp16 operands, fp32 accumulation.
// GEMM: CTA 128x128, 4 warps (64x64 warp tile), kblock 64, 3-stage cp.async,
// single-sync pipeline + interleaved fill quarters (R13 config — best known).
// Attention: log2-domain softmax (bias pre-scaled by log2e, ex2.approx) and
// DEFERRED normalization (1/sum applied at the output write, so the sum
// reduction overlaps the PV MMAs instead of gating them).
// ---------------------------------------------------------------------------

#define DIMC    512
#define NHEADS  16
#define HDIM    32
#define NTOK    49
#define NWIN    4096
#define MTOT    (NWIN * NTOK)          // 200704 = 1568 * 128 exactly

// Static device scratch (no runtime allocation allowed).
__device__ __align__(128) __half g_x_h[(size_t)MTOT * 512];
__device__ __align__(128) __half g_qkv_h[(size_t)MTOT * 1536];
__device__ __align__(128) __half g_attn_h[(size_t)MTOT * 512];
__device__ __align__(128) __half g_wq[(size_t)1536 * 512];     // qkv_w^T  [n][k]
__device__ __align__(128) __half g_wp[(size_t)512 * 512];      // proj_w^T [n][k]
__device__ __align__(128) __half g_biasp[NHEADS * 64 * 64];    // padded+masked bias * log2e

// ---------------------------------------------------------------------------
// helpers
// ---------------------------------------------------------------------------
__device__ __forceinline__ uint32_t smem_u32(const void* p) {
    uint32_t a;
    asm("{ .reg .u64 t; cvta.to.shared.u64 t, %1; cvt.u32.u64 %0, t; }" : "=r"(a) : "l"(p));
    return a;
}
__device__ __forceinline__ void mma16816(float c[4], const unsigned a[4], const unsigned b[2]) {
    asm volatile(
        "mma.sync.aligned.m16n8k16.row.col.f32.f16.f16.f32 "
        "{%0,%1,%2,%3}, {%4,%5,%6,%7}, {%8,%9}, {%0,%1,%2,%3};\n"
        : "+f"(c[0]), "+f"(c[1]), "+f"(c[2]), "+f"(c[3])
        : "r"(a[0]), "r"(a[1]), "r"(a[2]), "r"(a[3]), "r"(b[0]), "r"(b[1]));
}
__device__ __forceinline__ unsigned f2h2(float lo, float hi) {
    __half2 h = __floats2half2_rn(lo, hi);
    return *reinterpret_cast<unsigned*>(&h);
}
__device__ __forceinline__ float ex2f(float x) {
    float y;
    asm("ex2.approx.f32 %0, %1;" : "=f"(y) : "f"(x));
    return y;
}
#define LDSM_X4(r0, r1, r2, r3, addr) \
    asm volatile("ldmatrix.sync.aligned.m8n8.x4.shared.b16 {%0,%1,%2,%3}, [%4];" \
                 : "=r"(r0), "=r"(r1), "=r"(r2), "=r"(r3) : "r"(addr))
#define LDSM_X4T(r0, r1, r2, r3, addr) \
    asm volatile("ldmatrix.sync.aligned.m8n8.x4.trans.shared.b16 {%0,%1,%2,%3}, [%4];" \
                 : "=r"(r0), "=r"(r1), "=r"(r2), "=r"(r3) : "r"(addr))
#define CP_ASYNC16(dst, src) \
    asm volatile("cp.async.cg.shared.global [%0], [%1], 16;\n" :: "r"(dst), "l"(src))
#define CP_COMMIT() asm volatile("cp.async.commit_group;\n" ::: "memory")
#define CP_WAIT1()  asm volatile("cp.async.wait_group 1;\n" ::: "memory")
#define CP_WAIT0()  asm volatile("cp.async.wait_group 0;\n" ::: "memory")

// ---------------------------------------------------------------------------
// prepass kernels
// ---------------------------------------------------------------------------
__global__ void conv_x(const float* __restrict__ in, __half* __restrict__ out, int n4) {
    int i = blockIdx.x * blockDim.x + threadIdx.x;
    if (i < n4) {
        float4 v = reinterpret_cast<const float4*>(in)[i];
        uint2 o;
        o.x = f2h2(v.x, v.y);
        o.y = f2h2(v.z, v.w);
        reinterpret_cast<uint2*>(out)[i] = o;
    }
}
// w[K][Nw] fp32 -> wt[n][k] fp16, smem-tiled (coalesced both sides)
__global__ void conv_wT(const float* __restrict__ w, __half* __restrict__ wt, int K, int Nw) {
    __shared__ float tile[32][33];
    const int n0 = blockIdx.x * 32, k0 = blockIdx.y * 32;
    const int tx = threadIdx.x, ty = threadIdx.y;
#pragma unroll
    for (int i = ty; i < 32; i += 8)
        tile[i][tx] = w[(size_t)(k0 + i) * Nw + n0 + tx];
    __syncthreads();
#pragma unroll
    for (int i = ty; i < 32; i += 8)
        wt[(size_t)(n0 + i) * K + k0 + tx] = __float2half_rn(tile[tx][i]);
}
// gather + pad 49x49 -> 64x64 + mask, pre-scaled by log2e for exp2-domain
// softmax. Mask = -30000*log2e = -43281 (fp16-representable; exp2 -> 0).
#define LOG2E_F 1.4426950408889634f
__global__ void bias_gather(const float* __restrict__ table, const int* __restrict__ idx) {
    int h = blockIdx.x;
    for (int e = threadIdx.x; e < 64 * 64; e += blockDim.x) {
        int i = e >> 6, j = e & 63;
        float v = (i < NTOK && j < NTOK) ? table[idx[i * NTOK + j] * NHEADS + h] * LOG2E_F
                                         : -30000.f * LOG2E_F;
        g_biasp[h * 4096 + e] = __float2half_rn(v);
    }
}

// ---------------------------------------------------------------------------
// GEMM: C[M][Nn] = A[M][512](half) @ BT[Nn][512]^T + bias
// CTA tile 128x128, kblock 64, 4 warps (2x2), warp tile 64x64.
// smem per stage: A 16KB + B 16KB (swizzled 128B rows). 3 stages = 96KB.
// Single sync per iteration; fill issued in quarters inside compute steps.
// ---------------------------------------------------------------------------
#define STAGE_BYTES 32768
#define GEMM_SMEM   (3 * STAGE_BYTES)

__device__ __forceinline__ void fill_async(uint32_t stage,
                                           const __half* __restrict__ A,
                                           const __half* __restrict__ BT,
                                           int mBase, int nBase, int kb, int tid) {
#pragma unroll
    for (int q = 0; q < 8; q++) {
        int c = tid + q * 128;
        int row = c >> 3, ch = c & 7;
        const __half* src = A + (size_t)(mBase + row) * 512 + kb + ch * 8;
        uint32_t off = row * 128 + ((ch ^ (row & 7)) * 16);
        CP_ASYNC16(stage + off, src);
    }
#pragma unroll
    for (int q = 0; q < 8; q++) {
        int c = tid + q * 128;
        int row = c >> 3, ch = c & 7;
        const __half* src = BT + (size_t)(nBase + row) * 512 + kb + ch * 8;
        uint32_t off = row * 128 + ((ch ^ (row & 7)) * 16);
        CP_ASYNC16(stage + 16384 + off, src);
    }
}

// quarter q4 (0..3): A chunks 2*q4,2*q4+1 and B chunks 2*q4,2*q4+1
__device__ __forceinline__ void fill_quarter(uint32_t stage,
                                             const __half* __restrict__ A,
                                             const __half* __restrict__ BT,
                                             int mBase, int nBase, int kb,
                                             int tid, int q4) {
#pragma unroll
    for (int q = 2 * q4; q < 2 * q4 + 2; q++) {
        int c = tid + q * 128;
        int row = c >> 3, ch = c & 7;
        const __half* src = A + (size_t)(mBase + row) * 512 + kb + ch * 8;
        uint32_t off = row * 128 + ((ch ^ (row & 7)) * 16);
        CP_ASYNC16(stage + off, src);
    }
#pragma unroll
    for (int q = 2 * q4; q < 2 * q4 + 2; q++) {
        int c = tid + q * 128;
        int row = c >> 3, ch = c & 7;
        const __half* src = BT + (size_t)(nBase + row) * 512 + kb + ch * 8;
        uint32_t off = row * 128 + ((ch ^ (row & 7)) * 16);
        CP_ASYNC16(stage + 16384 + off, src);
    }
}

template <bool OUT_HALF>
__global__ __launch_bounds__(128, 2) void gemm_f16(
    const __half* __restrict__ A, const __half* __restrict__ BT,
    const float* __restrict__ bias, void* __restrict__ Cout, int Nn)
{
    extern __shared__ __align__(1024) char smem[];
    const uint32_t sb = smem_u32(smem);
    const int tid = threadIdx.x;
    const int w = tid >> 5, lane = tid & 31;
    const int wm = w >> 1, wn = w & 1;               // 2x2 warp grid, tile 64x64
    const int g = lane >> 2, t = lane & 3;
    const int mBase = blockIdx.y * 128;
    const int nBase = blockIdx.x * 128;

    float acc[4][8][4];
#pragma unroll
    for (int mi = 0; mi < 4; mi++)
#pragma unroll
        for (int ni = 0; ni < 8; ni++)
#pragma unroll
            for (int c = 0; c < 4; c++) acc[mi][ni][c] = 0.f;

    // prologue: fill stages 0,1
    fill_async(sb + 0 * STAGE_BYTES, A, BT, mBase, nBase, 0, tid);
    CP_COMMIT();
    fill_async(sb + 1 * STAGE_BYTES, A, BT, mBase, nBase, 64, tid);
    CP_COMMIT();

    const int rA = lane & 15;                        // ldmatrix A lane->row
    const int cA = lane >> 4;
    const int rB = (lane & 7) + ((lane >> 1) & 8);   // ldmatrix B lane->row
    const int cB = (lane >> 3) & 1;

    // single-sync pipeline; fill quarters issued inside the LDSM->MMA windows
#pragma unroll
    for (int it = 0; it < 8; ++it) {                 // K = 8 * 64
        if (it < 7) { CP_WAIT1(); } else { CP_WAIT0(); }
        __syncthreads();
        const uint32_t cst = sb + (it % 3) * STAGE_BYTES;
        const uint32_t fst = sb + ((it + 2) % 3) * STAGE_BYTES;
        const int fkb = (it + 2) * 64;
        const bool doFill = (it < 6);
        const uint32_t sA = cst, sB = cst + 16384;

#pragma unroll
        for (int step = 0; step < 4; ++step) {       // 4 x k16
            const int kc = step * 2;
            unsigned a[4][4];
#pragma unroll
            for (int mi = 0; mi < 4; mi++) {
                int row = wm * 64 + mi * 16 + rA;
                int ch = (kc + cA) ^ (row & 7);
                LDSM_X4(a[mi][0], a[mi][1], a[mi][2], a[mi][3], sA + row * 128 + ch * 16);
            }
            unsigned b[8][2];
#pragma unroll
            for (int nj = 0; nj < 4; nj++) {
                int row = wn * 64 + nj * 16 + rB;
                int ch = (kc + cB) ^ (row & 7);
                unsigned r0, r1, r2, r3;
                LDSM_X4(r0, r1, r2, r3, sB + row * 128 + ch * 16);
                b[nj * 2][0] = r0; b[nj * 2][1] = r1;
                b[nj * 2 + 1][0] = r2; b[nj * 2 + 1][1] = r3;
            }
            // fill quarter lands in the LDSM->MMA dependency window
            if (doFill)
                fill_quarter(fst, A, BT, mBase, nBase, fkb, tid, step);
#pragma unroll
            for (int mi = 0; mi < 4; mi++)
#pragma unroll
                for (int ni = 0; ni < 8; ni++)
                    mma16816(acc[mi][ni], a[mi], b[ni]);
        }
        if (doFill) CP_COMMIT();
    }

    // epilogue: + bias, store (all dims exact multiples -> no guards)
#pragma unroll
    for (int mi = 0; mi < 4; mi++) {
        int r0 = mBase + wm * 64 + mi * 16 + g;
#pragma unroll
        for (int ni = 0; ni < 8; ni++) {
            int c = nBase + wn * 64 + ni * 8 + 2 * t;
            float b0 = bias[c], b1 = bias[c + 1];
            if (OUT_HALF) {
                __half* o = reinterpret_cast<__half*>(Cout);
                *reinterpret_cast<unsigned*>(o + (size_t)r0 * Nn + c) =
                    f2h2(acc[mi][ni][0] + b0, acc[mi][ni][1] + b1);
                *reinterpret_cast<unsigned*>(o + (size_t)(r0 + 8) * Nn + c) =
                    f2h2(acc[mi][ni][2] + b0, acc[mi][ni][3] + b1);
            } else {
                float* o = reinterpret_cast<float*>(Cout);
                *reinterpret_cast<float2*>(o + (size_t)r0 * Nn + c) =
                    make_float2(acc[mi][ni][0] + b0, acc[mi][ni][1] + b1);
                *reinterpret_cast<float2*>(o + (size_t)(r0 + 8) * Nn + c) =
                    make_float2(acc[mi][ni][2] + b0, acc[mi][ni][3] + b1);
            }
        }
    }
}

// ---------------------------------------------------------------------------
// fused attention per (window, head). 4 warps, M/N padded 49->64.
// log2-domain softmax (bias pre-scaled by log2e), ex2.approx, and DEFERRED
// normalization: PV runs on unnormalized P; 1/sum applied at output write,
// so the sum reduction overlaps the PV MMAs.
// ---------------------------------------------------------------------------
__global__ __launch_bounds__(128) void attn_kernel()
{
    __shared__ __align__(16) __half sQ[64][40];   // [m][d]  (80B rows)
    __shared__ __align__(16) __half sK[64][40];   // [j][d]
    __shared__ __align__(16) __half sV[64][40];   // [j][d]

    const int win = blockIdx.x, head = blockIdx.y;
    const int tid = threadIdx.x;
    const int w = tid >> 5, lane = tid & 31;
    const int g = lane >> 2, t = lane & 3;
    const uint32_t qB = smem_u32(&sQ[0][0]);
    const uint32_t kB = smem_u32(&sK[0][0]);
    const uint32_t vB = smem_u32(&sV[0][0]);

    // zero only pad rows 48..63 (cols 0..31), all 3 arrays
    {
        const uint4 z4 = make_uint4(0u, 0u, 0u, 0u);
        for (int e = tid; e < 192; e += 128) {
            int a = e >> 6, r = 48 + ((e >> 2) & 15), c = e & 3;
            __half* base = (a == 0) ? &sQ[r][c * 8] : (a == 1) ? &sK[r][c * 8] : &sV[r][c * 8];
            *reinterpret_cast<uint4*>(base) = z4;
        }
    }
    __syncthreads();

    // load Q,K,V rows (49 rows x 4 x 16B each)
    const size_t rowbase = (size_t)(win * NTOK) * 1536;
    for (int e = tid; e < 588; e += 128) {
        int which = e / 196, ee = e - which * 196;
        int i = ee >> 2, c = ee & 3;
        uint4 v = *reinterpret_cast<const uint4*>(
            g_qkv_h + rowbase + (size_t)i * 1536 + which * 512 + head * HDIM + c * 8);
        __half* dst = (which == 0) ? &sQ[i][c * 8] : (which == 1) ? &sK[i][c * 8] : &sV[i][c * 8];
        *reinterpret_cast<uint4*>(dst) = v;
    }
    __syncthreads();

    // ---- S = Q K^T (per warp m16 x n64 x k32), ldmatrix fragments ----
    float sacc[8][4];
#pragma unroll
    for (int ni = 0; ni < 8; ni++)
#pragma unroll
        for (int c = 0; c < 4; c++) sacc[ni][c] = 0.f;

    const int rA = lane & 15, cA = lane >> 4;
    const int rB = (lane & 7) + ((lane >> 1) & 8), cB = (lane >> 3) & 1;
#pragma unroll
    for (int ks = 0; ks < 2; ++ks) {
        unsigned a[4];
        {
            int row = w * 16 + rA;
            LDSM_X4(a[0], a[1], a[2], a[3], qB + row * 80 + (ks * 2 + cA) * 16);
        }
        unsigned b[8][2];
#pragma unroll
        for (int nj = 0; nj < 4; nj++) {
            int row = nj * 16 + rB;
            unsigned r0v, r1v, r2v, r3v;
            LDSM_X4(r0v, r1v, r2v, r3v, kB + row * 80 + (ks * 2 + cB) * 16);
            b[nj * 2][0] = r0v; b[nj * 2][1] = r1v;
            b[nj * 2 + 1][0] = r2v; b[nj * 2 + 1][1] = r3v;
        }
#pragma unroll
        for (int ni = 0; ni < 8; ni++)
            mma16816(sacc[ni], a, b[ni]);
    }

    // ---- scale(log2e) + bias(log2e) + row max ----
    const float scale = 0.25505410402f;         // 32^-0.5 * log2(e)
    const int r0 = w * 16 + g;
    const __half* bp = g_biasp + head * 4096;
    float mA = -1e38f, mB = -1e38f;
#pragma unroll
    for (int ni = 0; ni < 8; ni++) {
        int c0 = ni * 8 + 2 * t;
        float2 bA = __half22float2(*reinterpret_cast<const __half2*>(bp + r0 * 64 + c0));
        float2 bBv = __half22float2(*reinterpret_cast<const __half2*>(bp + (r0 + 8) * 64 + c0));
        sacc[ni][0] = fmaf(sacc[ni][0], scale, bA.x);
        sacc[ni][1] = fmaf(sacc[ni][1], scale, bA.y);
        sacc[ni][2] = fmaf(sacc[ni][2], scale, bBv.x);
        sacc[ni][3] = fmaf(sacc[ni][3], scale, bBv.y);
        mA = fmaxf(mA, fmaxf(sacc[ni][0], sacc[ni][1]));
        mB = fmaxf(mB, fmaxf(sacc[ni][2], sacc[ni][3]));
    }
    mA = fmaxf(mA, __shfl_xor_sync(0xffffffffu, mA, 1));
    mA = fmaxf(mA, __shfl_xor_sync(0xffffffffu, mA, 2));
    mB = fmaxf(mB, __shfl_xor_sync(0xffffffffu, mB, 1));
    mB = fmaxf(mB, __shfl_xor_sync(0xffffffffu, mB, 2));

    // ---- exp2 (unnormalized P) ----
#pragma unroll
    for (int ni = 0; ni < 8; ni++) {
        sacc[ni][0] = ex2f(sacc[ni][0] - mA);
        sacc[ni][1] = ex2f(sacc[ni][1] - mA);
        sacc[ni][2] = ex2f(sacc[ni][2] - mB);
        sacc[ni][3] = ex2f(sacc[ni][3] - mB);
    }

    // ---- O = P_unnorm V (per warp m16 x n32 x k64); V via ldmatrix.trans ----
    float oacc[4][4];
#pragma unroll
    for (int ni = 0; ni < 4; ni++)
#pragma unroll
        for (int c = 0; c < 4; c++) oacc[ni][c] = 0.f;

    const int rV = (lane & 7) + (lane & 8);
    const int cV = (lane >> 4) << 3;
#pragma unroll
    for (int ks = 0; ks < 4; ++ks) {
        unsigned a[4];
        a[0] = f2h2(sacc[2 * ks][0], sacc[2 * ks][1]);
        a[1] = f2h2(sacc[2 * ks][2], sacc[2 * ks][3]);
        a[2] = f2h2(sacc[2 * ks + 1][0], sacc[2 * ks + 1][1]);
        a[3] = f2h2(sacc[2 * ks + 1][2], sacc[2 * ks + 1][3]);
        const int kk = ks * 16;
        unsigned b[4][2];
#pragma unroll
        for (int njp = 0; njp < 2; njp++) {
            unsigned r0v, r1v, r2v, r3v;
            LDSM_X4T(r0v, r1v, r2v, r3v,
                     vB + (kk + rV) * 80 + (njp * 16 + cV) * 2);
            b[njp * 2][0] = r0v; b[njp * 2][1] = r1v;
            b[njp * 2 + 1][0] = r2v; b[njp * 2 + 1][1] = r3v;
        }
#pragma unroll
        for (int ni = 0; ni < 4; ni++)
            mma16816(oacc[ni], a, b[ni]);
    }

    // ---- sum reduction (overlaps PV above in the scheduler) ----
    float sumA = 0.f, sumB = 0.f;
#pragma unroll
    for (int ni = 0; ni < 8; ni++) {
        sumA += sacc[ni][0] + sacc[ni][1];
        sumB += sacc[ni][2] + sacc[ni][3];
    }
    sumA += __shfl_xor_sync(0xffffffffu, sumA, 1);
    sumA += __shfl_xor_sync(0xffffffffu, sumA, 2);
    sumB += __shfl_xor_sync(0xffffffffu, sumB, 1);
    sumB += __shfl_xor_sync(0xffffffffu, sumB, 2);
    const float invA = 1.f / sumA, invB = 1.f / sumB;

    // ---- write attn-out (half) rows < 49, normalized here ----
    if (r0 < NTOK) {
        size_t gr = (size_t)(win * NTOK + r0) * 512 + head * HDIM;
#pragma unroll
        for (int ni = 0; ni < 4; ni++)
            *reinterpret_cast<unsigned*>(g_attn_h + gr + ni * 8 + 2 * t) =
                f2h2(oacc[ni][0] * invA, oacc[ni][1] * invA);
    }
    if (r0 + 8 < NTOK) {
        size_t gr = (size_t)(win * NTOK + r0 + 8) * 512 + head * HDIM;
#pragma unroll
        for (int ni = 0; ni < 4; ni++)
            *reinterpret_cast<unsigned*>(g_attn_h + gr + ni * 8 + 2 * t) =
                f2h2(oacc[ni][2] * invB, oacc[ni][3] * invB);
    }
}

// ---------------------------------------------------------------------------
extern "C" void kernel_launch(void* const* d_in, const int* in_sizes, int n_in,
                              void* d_out, int out_size)
{
    const float* x      = (const float*)d_in[0];
    const float* qkv_w  = (const float*)d_in[1];
    const float* qkv_b  = (const float*)d_in[2];
    const float* proj_w = (const float*)d_in[3];
    const float* proj_b = (const float*)d_in[4];
    const float* table  = (const float*)d_in[5];
    const int*   rpi    = (const int*)d_in[6];
    float* out = (float*)d_out;

    void *xh, *qkvh, *attnh, *wq, *wp;
    cudaGetSymbolAddress(&xh, g_x_h);
    cudaGetSymbolAddress(&qkvh, g_qkv_h);
    cudaGetSymbolAddress(&attnh, g_attn_h);
    cudaGetSymbolAddress(&wq, g_wq);
    cudaGetSymbolAddress(&wp, g_wp);

    cudaFuncSetAttribute(gemm_f16<true>,  cudaFuncAttributeMaxDynamicSharedMemorySize, GEMM_SMEM);
    cudaFuncSetAttribute(gemm_f16<false>, cudaFuncAttributeMaxDynamicSharedMemorySize, GEMM_SMEM);

    const int n4 = MTOT * 512 / 4;
    conv_x<<<n4 / 256, 256>>>(x, (__half*)xh, n4);
    conv_wT<<<dim3(1536 / 32, 512 / 32), dim3(32, 8)>>>(qkv_w, (__half*)wq, 512, 1536);
    conv_wT<<<dim3(512 / 32, 512 / 32), dim3(32, 8)>>>(proj_w, (__half*)wp, 512, 512);
    bias_gather<<<NHEADS, 256>>>(table, rpi);

    gemm_f16<true><<<dim3(1536 / 128, MTOT / 128), 128, GEMM_SMEM>>>(
        (const __half*)xh, (const __half*)wq, qkv_b, qkvh, 1536);
    attn_kernel<<<dim3(NWIN, NHEADS), 128>>>();
    gemm_f16<false><<<dim3(512 / 128, MTOT / 128), 128, GEMM_SMEM>>>(
        (const __half*)attnh, (const __half*)wp, proj_b, out, 512);
}